// round 2
// baseline (speedup 1.0000x reference)
#include <cuda_runtime.h>
#include <math.h>

#define Bc 2
#define Sc 2048
#define Ec 1024
#define Hc 16
#define Dc 64
#define BSc (Bc*Sc)

// ---------------- scratch (device globals: allocation-free, ~80MB total) ----------------
__device__ __align__(128) float g_q[Bc*Sc*Ec];
__device__ __align__(128) float g_k[Bc*Sc*Ec];
__device__ __align__(128) float g_v[Bc*Sc*Ec];
__device__ __align__(128) float g_g[Bc*Sc*Ec];
__device__ __align__(128) float g_av[Bc*Sc*Ec];
__device__ __align__(128) float g_sin[Sc*Dc];
__device__ __align__(128) float g_cos[Sc*Dc];
__device__ __align__(128) float g_invnorm[Hc*Sc];

// ---------------- precompute: sin/cos tables ----------------
__global__ void k_sincos() {
    int i = blockIdx.x * blockDim.x + threadIdx.x;
    if (i >= Sc * Dc) return;
    int s = i / Dc, d = i % Dc;
    float a = powf(10000.0f, -(float)(d >> 1) / (float)(Dc / 2 - 1));
    float ang = (float)s * a;
    g_sin[i] = sinf(ang);
    g_cos[i] = cosf(ang);
}

// ---------------- precompute: mask row normalizers 1/sqrt(sum_k exp((q-k)*decay)) ----------------
__global__ void k_norm() {
    int h = blockIdx.x;
    float r = 1.0f - exp2f(-(float)(5 + h));   // exp(decay[h]) exactly
    for (int q = threadIdx.x; q < Sc; q += blockDim.x) {
        float sum = 0.0f, p = 1.0f;
        for (int j = 0; j <= q; ++j) { sum += p; p *= r; }
        g_invnorm[h * Sc + q] = rsqrtf(sum);
    }
}

// ---------------- fused Q/K/V/G projections: O = X @ W (* scale for K) ----------------
__global__ __launch_bounds__(256) void k_gemm_qkvg(
    const float* __restrict__ X,
    const float* __restrict__ Wq, const float* __restrict__ Wk,
    const float* __restrict__ Wv, const float* __restrict__ Wg)
{
    const int z = blockIdx.z;
    const float* W = (z == 0) ? Wq : (z == 1) ? Wk : (z == 2) ? Wv : Wg;
    float* O       = (z == 0) ? g_q : (z == 1) ? g_k : (z == 2) ? g_v : g_g;
    const float scale = (z == 1) ? 0.03125f : 1.0f;   // E^-0.5 on K

    __shared__ float As[16][128];
    __shared__ float Bs[16][128];
    int tid = threadIdx.x;
    int tx = tid & 15, ty = tid >> 4;
    int rowBase = blockIdx.y * 128;
    int colBase = blockIdx.x * 128;

    float acc[8][8];
#pragma unroll
    for (int m = 0; m < 8; ++m)
#pragma unroll
        for (int n = 0; n < 8; ++n) acc[m][n] = 0.0f;

    for (int kt = 0; kt < Ec; kt += 16) {
#pragma unroll
        for (int i = 0; i < 2; ++i) {
            int lin = tid + i * 256;
            int r = lin >> 2, c4 = lin & 3;
            float4 a = *(const float4*)&X[(size_t)(rowBase + r) * Ec + kt + c4 * 4];
            As[c4 * 4 + 0][r] = a.x; As[c4 * 4 + 1][r] = a.y;
            As[c4 * 4 + 2][r] = a.z; As[c4 * 4 + 3][r] = a.w;
        }
#pragma unroll
        for (int i = 0; i < 2; ++i) {
            int lin = tid + i * 256;
            int r = lin >> 5, c4 = lin & 31;
            *(float4*)&Bs[r][c4 * 4] =
                *(const float4*)&W[(size_t)(kt + r) * Ec + colBase + c4 * 4];
        }
        __syncthreads();
#pragma unroll
        for (int kk = 0; kk < 16; ++kk) {
            float ra[8], rb[8];
            *(float4*)&ra[0] = *(float4*)&As[kk][ty * 8];
            *(float4*)&ra[4] = *(float4*)&As[kk][ty * 8 + 4];
            *(float4*)&rb[0] = *(float4*)&Bs[kk][tx * 8];
            *(float4*)&rb[4] = *(float4*)&Bs[kk][tx * 8 + 4];
#pragma unroll
            for (int m = 0; m < 8; ++m)
#pragma unroll
                for (int n = 0; n < 8; ++n) acc[m][n] += ra[m] * rb[n];
        }
        __syncthreads();
    }
#pragma unroll
    for (int m = 0; m < 8; ++m) {
        int r = rowBase + ty * 8 + m;
#pragma unroll
        for (int n4 = 0; n4 < 2; ++n4) {
            float4 o;
            o.x = acc[m][n4 * 4 + 0] * scale;
            o.y = acc[m][n4 * 4 + 1] * scale;
            o.z = acc[m][n4 * 4 + 2] * scale;
            o.w = acc[m][n4 * 4 + 3] * scale;
            *(float4*)&O[(size_t)r * Ec + colBase + tx * 8 + n4 * 4] = o;
        }
    }
}

// ---------------- rotary theta-shift on q,k in place ----------------
__global__ void k_theta() {
    int i = blockIdx.x * blockDim.x + threadIdx.x;   // pair index
    if (i >= Bc * Sc * Ec / 2) return;
    int e2 = i % (Ec / 2);
    int bs = i / (Ec / 2);
    int e = e2 * 2;
    int d = e & (Dc - 1);
    int s = bs % Sc;
    float sn0 = g_sin[s * Dc + d],     sn1 = g_sin[s * Dc + d + 1];
    float cs0 = g_cos[s * Dc + d],     cs1 = g_cos[s * Dc + d + 1];
    size_t idx = (size_t)bs * Ec + e;
    float q0 = g_q[idx], q1 = g_q[idx + 1];
    g_q[idx]     = q0 * cs0 - q1 * sn0;
    g_q[idx + 1] = q1 * cs1 + q0 * sn1;
    float k0 = g_k[idx], k1 = g_k[idx + 1];
    g_k[idx]     = k0 * cs0 - k1 * sn0;
    g_k[idx + 1] = k1 * cs1 + k0 * sn1;
}

// ---------------- fused retention: S = QK^T * mask ; denom ; O = (S/denom) @ V ----------------
// smem layout (floats):
//   Qs [64][128]  (Qs[k][row])      8192
//   Ks [64][128]  (Ks[k][col])      8192
//   Vs [128][64]  (Vs[col][d])      8192
//   Ss [128][132] (Ss[row][col])   16896
#define SM_QS 0
#define SM_KS 8192
#define SM_VS 16384
#define SM_SS 24576
#define SM_FLOATS (24576 + 128*132)
#define SM_BYTES (SM_FLOATS * 4)

__global__ __launch_bounds__(256) void k_retention() {
    extern __shared__ float sm[];
    float* Qs = sm + SM_QS;
    float* Ks = sm + SM_KS;
    float* Vs = sm + SM_VS;
    float* Ss = sm + SM_SS;

    int bh = blockIdx.z;
    int b = bh >> 4, h = bh & 15;
    int qTile = (int)(gridDim.y - 1) - (int)blockIdx.y;   // heavy tiles first
    int tid = threadIdx.x;
    int tx = tid & 15, ty = tid >> 4;
    int qRow0 = qTile * 128;

    const float* Qg = g_q + (size_t)b * Sc * Ec + h * Dc;
    const float* Kg = g_k + (size_t)b * Sc * Ec + h * Dc;
    const float* Vg = g_v + (size_t)b * Sc * Ec + h * Dc;

    // load Q tile transposed (conflict-free smem stores; 16B-granule gmem loads)
#pragma unroll
    for (int i = 0; i < 8; ++i) {
        int lin = tid + i * 256;          // 0..2047 float4 slots
        int r = lin & 127, c4 = lin >> 7; // c4 0..15 -> k = c4*4
        float4 a = *(const float4*)&Qg[(size_t)(qRow0 + r) * Ec + c4 * 4];
        Qs[(c4 * 4 + 0) * 128 + r] = a.x;
        Qs[(c4 * 4 + 1) * 128 + r] = a.y;
        Qs[(c4 * 4 + 2) * 128 + r] = a.z;
        Qs[(c4 * 4 + 3) * 128 + r] = a.w;
    }

    float decay = logf(1.0f - exp2f(-(float)(5 + h)));
    float pwneg[8];                       // r^(-n) = exp(-n*decay)
#pragma unroll
    for (int n = 0; n < 8; ++n) pwneg[n] = expf(-(float)n * decay);
    float invn[8];
#pragma unroll
    for (int m = 0; m < 8; ++m) invn[m] = g_invnorm[h * Sc + qRow0 + ty * 8 + m];

    float acc2[8][4];
    float rowsum[8];
#pragma unroll
    for (int m = 0; m < 8; ++m) {
        rowsum[m] = 0.0f;
#pragma unroll
        for (int n = 0; n < 4; ++n) acc2[m][n] = 0.0f;
    }

    __syncthreads();   // Qs visible

    for (int kt = 0; kt <= qTile; ++kt) {
        int kcol0 = kt * 128;
        // load K tile (transposed) and V tile (natural)
#pragma unroll
        for (int i = 0; i < 8; ++i) {
            int lin = tid + i * 256;
            int c = lin & 127, c4 = lin >> 7;
            float4 a = *(const float4*)&Kg[(size_t)(kcol0 + c) * Ec + c4 * 4];
            Ks[(c4 * 4 + 0) * 128 + c] = a.x;
            Ks[(c4 * 4 + 1) * 128 + c] = a.y;
            Ks[(c4 * 4 + 2) * 128 + c] = a.z;
            Ks[(c4 * 4 + 3) * 128 + c] = a.w;
        }
#pragma unroll
        for (int i = 0; i < 8; ++i) {
            int lin = tid + i * 256;
            int c = lin >> 4, d4 = lin & 15;
            *(float4*)&Vs[c * 64 + d4 * 4] =
                *(const float4*)&Vg[(size_t)(kcol0 + c) * Ec + d4 * 4];
        }
        __syncthreads();

        // ---- GEMM1: S[128][128] = Q @ K^T ----
        float acc[8][8];
#pragma unroll
        for (int m = 0; m < 8; ++m)
#pragma unroll
            for (int n = 0; n < 8; ++n) acc[m][n] = 0.0f;
#pragma unroll 4
        for (int kk = 0; kk < 64; ++kk) {
            float ra[8], rb[8];
            *(float4*)&ra[0] = *(float4*)&Qs[kk * 128 + ty * 8];
            *(float4*)&ra[4] = *(float4*)&Qs[kk * 128 + ty * 8 + 4];
            *(float4*)&rb[0] = *(float4*)&Ks[kk * 128 + tx * 8];
            *(float4*)&rb[4] = *(float4*)&Ks[kk * 128 + tx * 8 + 4];
#pragma unroll
            for (int m = 0; m < 8; ++m)
#pragma unroll
                for (int n = 0; n < 8; ++n) acc[m][n] += ra[m] * rb[n];
        }

        // ---- mask, row-|S| reduce, stage S ----
#pragma unroll
        for (int m = 0; m < 8; ++m) {
            int q = qRow0 + ty * 8 + m;
            int kbase = kcol0 + tx * 8;
            // R_m = exp((q - kbase)*decay) * invnorm ; element n uses R_m * r^(-? )
            float Rm = expf((float)(q - kbase) * decay) * invn[m];
            float vals[8];
            float ls = 0.0f;
#pragma unroll
            for (int n = 0; n < 8; ++n) {
                float v = 0.0f;
                if (kbase + n <= q) v = acc[m][n] * (Rm * pwneg[n]);
                vals[n] = v;
                ls += fabsf(v);
            }
#pragma unroll
            for (int off = 1; off < 16; off <<= 1)
                ls += __shfl_xor_sync(0xffffffffu, ls, off, 16);
            rowsum[m] += ls;
            *(float4*)&Ss[(ty * 8 + m) * 132 + tx * 8]     = *(float4*)&vals[0];
            *(float4*)&Ss[(ty * 8 + m) * 132 + tx * 8 + 4] = *(float4*)&vals[4];
        }
        __syncthreads();

        // ---- GEMM2: O += S @ V ----
#pragma unroll 4
        for (int kc = 0; kc < 128; ++kc) {
            float rb[4];
            *(float4*)&rb[0] = *(float4*)&Vs[kc * 64 + tx * 4];
#pragma unroll
            for (int m = 0; m < 8; ++m) {
                float ra = Ss[(ty * 8 + m) * 132 + kc];
#pragma unroll
                for (int n = 0; n < 4; ++n) acc2[m][n] += ra * rb[n];
            }
        }
        __syncthreads();
    }

    // ---- epilogue: divide by clipped denom, write ----
#pragma unroll
    for (int m = 0; m < 8; ++m) {
        int q = qRow0 + ty * 8 + m;
        float den = fminf(fmaxf(rowsum[m], 1.0f), 50000.0f);
        float inv = 1.0f / den;
        float4 o;
        o.x = acc2[m][0] * inv; o.y = acc2[m][1] * inv;
        o.z = acc2[m][2] * inv; o.w = acc2[m][3] * inv;
        *(float4*)&g_av[(size_t)(b * Sc + q) * Ec + h * Dc + tx * 4] = o;
    }
}

// ---------------- RMSNorm over D, silu(g) gate, write output ----------------
__global__ void k_final(float* __restrict__ out) {
    __shared__ float warpsum[2];
    int bsh = blockIdx.x;            // (b*S+s)*H + h
    int h = bsh & (Hc - 1);
    int bs = bsh >> 4;
    int d = threadIdx.x;
    size_t idx = (size_t)bs * Ec + h * Dc + d;
    float v = g_av[idx];
    float sq = v * v;
#pragma unroll
    for (int off = 16; off; off >>= 1) sq += __shfl_down_sync(0xffffffffu, sq, off);
    if ((d & 31) == 0) warpsum[d >> 5] = sq;
    __syncthreads();
    float total = warpsum[0] + warpsum[1];
    float scl = rsqrtf(total * (1.0f / 64.0f) + 1e-6f);
    float gg = g_g[idx];
    float silu = gg / (1.0f + expf(-gg));
    out[idx] = silu * v * scl;
}

// ---------------- launch ----------------
extern "C" void kernel_launch(void* const* d_in, const int* in_sizes, int n_in,
                              void* d_out, int out_size) {
    const float* x  = (const float*)d_in[0];
    const float* Wq = (const float*)d_in[1];
    const float* Wk = (const float*)d_in[2];
    const float* Wv = (const float*)d_in[3];
    const float* Wg = (const float*)d_in[4];
    float* out = (float*)d_out;

    cudaFuncSetAttribute(k_retention, cudaFuncAttributeMaxDynamicSharedMemorySize, SM_BYTES);

    k_sincos<<<(Sc * Dc + 255) / 256, 256>>>();
    k_norm<<<Hc, 256>>>();

    dim3 gproj(Ec / 128, BSc / 128, 4);
    k_gemm_qkvg<<<gproj, 256>>>(x, Wq, Wk, Wv, Wg);

    k_theta<<<(Bc * Sc * Ec / 2 + 255) / 256, 256>>>();

    k_retention<<<dim3(1, Sc / 128, Bc * Hc), 256, SM_BYTES>>>();

    k_final<<<Bc * Sc * Hc, Dc>>>(out);
}

// round 5
// speedup vs baseline: 1.3147x; 1.3147x over previous
#include <cuda_runtime.h>
#include <cuda_bf16.h>
#include <math.h>
#include <stdint.h>

#define Bc 2
#define Sc 2048
#define Ec 1024
#define Hc 16
#define Dc 64
#define BSc (Bc*Sc)

// ---------------- scratch (device globals: allocation-free) ----------------
__device__ __align__(128) float g_q[BSc*Ec];
__device__ __align__(128) float g_k[BSc*Ec];
__device__ __align__(128) float g_v[BSc*Ec];
__device__ __align__(128) float g_g[BSc*Ec];
__device__ __align__(128) float g_av[BSc*Ec];
__device__ __align__(128) float g_sin[Sc*Dc];
__device__ __align__(128) float g_cos[Sc*Dc];
__device__ __align__(128) float g_invnorm[Hc*Sc];
__device__ __align__(128) __nv_bfloat16 g_xh[BSc*Ec];
__device__ __align__(128) __nv_bfloat16 g_xl[BSc*Ec];
__device__ __align__(128) __nv_bfloat16 g_wh[4*Ec*Ec];   // transposed [z][n][k]
__device__ __align__(128) __nv_bfloat16 g_wl[4*Ec*Ec];

// ---------------- warp-mma helpers (baseline PTX: sm_80+, no 'a' feature) ----------------
__device__ __forceinline__ uint32_t smem_u32(const void* p) {
    uint32_t a;
    asm("{ .reg .u64 t; cvta.to.shared.u64 t, %1; cvt.u32.u64 %0, t; }" : "=r"(a) : "l"(p));
    return a;
}
__device__ __forceinline__ void ldsm_x4(uint32_t& r0, uint32_t& r1, uint32_t& r2, uint32_t& r3,
                                        uint32_t addr) {
    asm volatile("ldmatrix.sync.aligned.m8n8.x4.shared.b16 {%0,%1,%2,%3}, [%4];"
                 : "=r"(r0), "=r"(r1), "=r"(r2), "=r"(r3) : "r"(addr));
}
__device__ __forceinline__ void mma_bf16(float* d, uint32_t a0, uint32_t a1, uint32_t a2,
                                         uint32_t a3, uint32_t b0, uint32_t b1) {
    asm volatile("mma.sync.aligned.m16n8k16.row.col.f32.bf16.bf16.f32 "
                 "{%0,%1,%2,%3}, {%4,%5,%6,%7}, {%8,%9}, {%0,%1,%2,%3};"
                 : "+f"(d[0]), "+f"(d[1]), "+f"(d[2]), "+f"(d[3])
                 : "r"(a0), "r"(a1), "r"(a2), "r"(a3), "r"(b0), "r"(b1));
}

// ---------------- precompute: sin/cos tables ----------------
__global__ void k_sincos() {
    int i = blockIdx.x * blockDim.x + threadIdx.x;
    if (i >= Sc * Dc) return;
    int s = i / Dc, d = i % Dc;
    float a = powf(10000.0f, -(float)(d >> 1) / (float)(Dc / 2 - 1));
    float ang = (float)s * a;
    g_sin[i] = sinf(ang);
    g_cos[i] = cosf(ang);
}

// ---------------- precompute: mask row normalizers ----------------
__global__ void k_norm() {
    int h = blockIdx.x;
    float r = 1.0f - exp2f(-(float)(5 + h));
    for (int q = threadIdx.x; q < Sc; q += blockDim.x) {
        float sum = 0.0f, p = 1.0f;
        for (int j = 0; j <= q; ++j) { sum += p; p *= r; }
        g_invnorm[h * Sc + q] = rsqrtf(sum);
    }
}

// ---------------- split X into bf16 hi/lo ----------------
__global__ void k_split_x(const float* __restrict__ X) {
    int i = blockIdx.x * 256 + threadIdx.x;
    float x = X[i];
    __nv_bfloat16 h = __float2bfloat16(x);
    g_xh[i] = h;
    g_xl[i] = __float2bfloat16(x - __bfloat162float(h));
}

// ---------------- transpose + split weights into bf16 hi/lo [n][k] ----------------
__global__ void k_split_w(const float* __restrict__ Wq, const float* __restrict__ Wk,
                          const float* __restrict__ Wv, const float* __restrict__ Wg) {
    __shared__ float t[32][33];
    int z = blockIdx.z;
    const float* W = (z == 0) ? Wq : (z == 1) ? Wk : (z == 2) ? Wv : Wg;
    int n0 = blockIdx.x * 32, k0 = blockIdx.y * 32;
    int tx = threadIdx.x, ty = threadIdx.y;   // 32 x 8
#pragma unroll
    for (int i = 0; i < 4; ++i)
        t[ty + i * 8][tx] = W[(size_t)(k0 + ty + i * 8) * Ec + n0 + tx];
    __syncthreads();
    size_t base = (size_t)z * Ec * Ec;
#pragma unroll
    for (int i = 0; i < 4; ++i) {
        float x = t[tx][ty + i * 8];
        __nv_bfloat16 h = __float2bfloat16(x);
        size_t idx = base + (size_t)(n0 + ty + i * 8) * Ec + k0 + tx;
        g_wh[idx] = h;
        g_wl[idx] = __float2bfloat16(x - __bfloat162float(h));
    }
}

// ---------------- tensor-core projections via mma.sync ----------------
// CTA 128x128, 8 warps (warp tile 32x64), k-chunk 32, double-buffered smem
// smem rows padded to 40 bf16 (80 B) => ldmatrix conflict-free.
#define KCH 32
#define LDSW 40
#define NCHUNK 96   // 3 split-terms x (1024/32)

__global__ __launch_bounds__(256) void k_gemm_mma() {
    __shared__ __nv_bfloat16 smA[2][128 * LDSW];
    __shared__ __nv_bfloat16 smB[2][128 * LDSW];

    const int tid = threadIdx.x;
    const int wid = tid >> 5, lane = tid & 31;
    const int z = blockIdx.z;
    const int rowBase = blockIdx.y * 128;
    const int colBase = blockIdx.x * 128;

    const __nv_bfloat16* Wh = g_wh + (size_t)z * Ec * Ec;
    const __nv_bfloat16* Wl = g_wl + (size_t)z * Ec * Ec;
    float* O = (z == 0) ? g_q : (z == 1) ? g_k : (z == 2) ? g_v : g_g;
    const float scale = (z == 1) ? 0.03125f : 1.0f;

    const int warpM = wid & 3;     // 4 x 32 rows
    const int warpN = wid >> 2;    // 2 x 64 cols

    float acc[2][8][4];
#pragma unroll
    for (int mi = 0; mi < 2; ++mi)
#pragma unroll
        for (int nj = 0; nj < 8; ++nj)
#pragma unroll
            for (int e = 0; e < 4; ++e) acc[mi][nj][e] = 0.0f;

    // ldmatrix lane address pattern: tile t = lane>>3, r = lane&7
    const int lt = lane >> 3, lr = lane & 7;
    // row-within-16 = (t&1)*8 + r ; k-half = (t>>1)*8
    const int ldsmRow = (lt & 1) * 8 + lr;
    const int ldsmKB  = (lt >> 1) * 16;          // bytes (8 bf16)
    uint32_t baseA = smem_u32(&smA[0][0]);
    uint32_t baseB = smem_u32(&smB[0][0]);
    // per-buffer byte offset
    const uint32_t BUFB = 128 * LDSW * 2;

    // loader indices: 512 uint4 per tile, 2 per thread
    const int l0 = tid, l1 = tid + 256;
    const int l0r = l0 >> 2, l0i = l0 & 3;
    const int l1r = l1 >> 2, l1i = l1 & 3;

    // ---- fill chunk 0 into buf 0 ----
    {
        const __nv_bfloat16* Ag = g_xh + (size_t)rowBase * Ec;      // chunk0: blk0, kk0=0
        const __nv_bfloat16* Bg = Wh + (size_t)colBase * Ec;
        *(uint4*)((char*)&smA[0][0] + l0r * 80 + l0i * 16) = *(const uint4*)(Ag + (size_t)l0r * Ec + l0i * 8);
        *(uint4*)((char*)&smA[0][0] + l1r * 80 + l1i * 16) = *(const uint4*)(Ag + (size_t)l1r * Ec + l1i * 8);
        *(uint4*)((char*)&smB[0][0] + l0r * 80 + l0i * 16) = *(const uint4*)(Bg + (size_t)l0r * Ec + l0i * 8);
        *(uint4*)((char*)&smB[0][0] + l1r * 80 + l1i * 16) = *(const uint4*)(Bg + (size_t)l1r * Ec + l1i * 8);
    }
    __syncthreads();

    for (int c = 0; c < NCHUNK; ++c) {
        int buf = c & 1;
        // ---- prefetch next chunk to registers ----
        uint4 tA0, tA1, tB0, tB1;
        bool hasNext = (c + 1 < NCHUNK);
        if (hasNext) {
            int cn = c + 1;
            int blk = cn >> 5;
            int kk0 = (cn & 31) * KCH;
            const __nv_bfloat16* Ag = ((blk < 2) ? g_xh : g_xl) + (size_t)rowBase * Ec + kk0;
            const __nv_bfloat16* Bg = ((blk == 1) ? Wl : Wh) + (size_t)colBase * Ec + kk0;
            tA0 = *(const uint4*)(Ag + (size_t)l0r * Ec + l0i * 8);
            tA1 = *(const uint4*)(Ag + (size_t)l1r * Ec + l1i * 8);
            tB0 = *(const uint4*)(Bg + (size_t)l0r * Ec + l0i * 8);
            tB1 = *(const uint4*)(Bg + (size_t)l1r * Ec + l1i * 8);
        }

        // ---- compute: 2 k16 steps ----
        uint32_t bufA = baseA + buf * BUFB;
        uint32_t bufB = baseB + buf * BUFB;
#pragma unroll
        for (int s = 0; s < 2; ++s) {
            int kB = s * 32 + ldsmKB;    // byte offset of k-half
            uint32_t a[2][4];
#pragma unroll
            for (int mi = 0; mi < 2; ++mi) {
                uint32_t addr = bufA + (warpM * 32 + mi * 16 + ldsmRow) * 80 + kB;
                ldsm_x4(a[mi][0], a[mi][1], a[mi][2], a[mi][3], addr);
            }
            uint32_t bt[4][4];
#pragma unroll
            for (int ni = 0; ni < 4; ++ni) {
                uint32_t addr = bufB + (warpN * 64 + ni * 16 + ldsmRow) * 80 + kB;
                ldsm_x4(bt[ni][0], bt[ni][1], bt[ni][2], bt[ni][3], addr);
            }
#pragma unroll
            for (int mi = 0; mi < 2; ++mi)
#pragma unroll
                for (int ni = 0; ni < 4; ++ni) {
                    mma_bf16(acc[mi][ni * 2 + 0], a[mi][0], a[mi][1], a[mi][2], a[mi][3],
                             bt[ni][0], bt[ni][2]);
                    mma_bf16(acc[mi][ni * 2 + 1], a[mi][0], a[mi][1], a[mi][2], a[mi][3],
                             bt[ni][1], bt[ni][3]);
                }
        }

        // ---- commit prefetched regs to the other buffer ----
        if (hasNext) {
            int nb = buf ^ 1;
            *(uint4*)((char*)&smA[nb][0] + l0r * 80 + l0i * 16) = tA0;
            *(uint4*)((char*)&smA[nb][0] + l1r * 80 + l1i * 16) = tA1;
            *(uint4*)((char*)&smB[nb][0] + l0r * 80 + l0i * 16) = tB0;
            *(uint4*)((char*)&smB[nb][0] + l1r * 80 + l1i * 16) = tB1;
        }
        __syncthreads();
    }

    // ---- epilogue ----
    const int mrow = rowBase + warpM * 32 + (lane >> 2);
    const int mcol = colBase + warpN * 64 + (lane & 3) * 2;
#pragma unroll
    for (int mi = 0; mi < 2; ++mi)
#pragma unroll
        for (int nj = 0; nj < 8; ++nj) {
            int r0 = mrow + mi * 16;
            int c0 = mcol + nj * 8;
            float2 v0 = { acc[mi][nj][0] * scale, acc[mi][nj][1] * scale };
            float2 v1 = { acc[mi][nj][2] * scale, acc[mi][nj][3] * scale };
            *(float2*)&O[(size_t)r0 * Ec + c0]       = v0;
            *(float2*)&O[(size_t)(r0 + 8) * Ec + c0] = v1;
        }
}

// ---------------- rotary theta-shift on q,k in place ----------------
__global__ void k_theta() {
    int i = blockIdx.x * blockDim.x + threadIdx.x;
    if (i >= BSc * Ec / 2) return;
    int e2 = i % (Ec / 2);
    int bs = i / (Ec / 2);
    int e = e2 * 2;
    int d = e & (Dc - 1);
    int s = bs % Sc;
    float sn0 = g_sin[s * Dc + d], sn1 = g_sin[s * Dc + d + 1];
    float cs0 = g_cos[s * Dc + d], cs1 = g_cos[s * Dc + d + 1];
    size_t idx = (size_t)bs * Ec + e;
    float q0 = g_q[idx], q1 = g_q[idx + 1];
    g_q[idx]     = q0 * cs0 - q1 * sn0;
    g_q[idx + 1] = q1 * cs1 + q0 * sn1;
    float k0 = g_k[idx], k1 = g_k[idx + 1];
    g_k[idx]     = k0 * cs0 - k1 * sn0;
    g_k[idx + 1] = k1 * cs1 + k0 * sn1;
}

// ---------------- fused retention (flash-style, fp32) ----------------
#define SM_QS 0
#define SM_KS 8192
#define SM_VS 16384
#define SM_SS 24576
#define SM_FLOATS (24576 + 128*132)
#define SM_BYTES (SM_FLOATS * 4)

__global__ __launch_bounds__(256) void k_retention() {
    extern __shared__ float smf[];
    float* Qs = smf + SM_QS;
    float* Ks = smf + SM_KS;
    float* Vs = smf + SM_VS;
    float* Ss = smf + SM_SS;

    int bh = blockIdx.z;
    int b = bh >> 4, h = bh & 15;
    int qTile = (int)(gridDim.y - 1) - (int)blockIdx.y;
    int tid = threadIdx.x;
    int tx = tid & 15, ty = tid >> 4;
    int qRow0 = qTile * 128;

    const float* Qg = g_q + (size_t)b * Sc * Ec + h * Dc;
    const float* Kg = g_k + (size_t)b * Sc * Ec + h * Dc;
    const float* Vg = g_v + (size_t)b * Sc * Ec + h * Dc;

#pragma unroll
    for (int i = 0; i < 8; ++i) {
        int lin = tid + i * 256;
        int r = lin & 127, c4 = lin >> 7;
        float4 a = *(const float4*)&Qg[(size_t)(qRow0 + r) * Ec + c4 * 4];
        Qs[(c4 * 4 + 0) * 128 + r] = a.x;
        Qs[(c4 * 4 + 1) * 128 + r] = a.y;
        Qs[(c4 * 4 + 2) * 128 + r] = a.z;
        Qs[(c4 * 4 + 3) * 128 + r] = a.w;
    }

    float decay = logf(1.0f - exp2f(-(float)(5 + h)));
    float pwneg[8];
#pragma unroll
    for (int n = 0; n < 8; ++n) pwneg[n] = expf(-(float)n * decay);
    float invn[8];
#pragma unroll
    for (int m = 0; m < 8; ++m) invn[m] = g_invnorm[h * Sc + qRow0 + ty * 8 + m];

    float acc2[8][4];
    float rowsum[8];
#pragma unroll
    for (int m = 0; m < 8; ++m) {
        rowsum[m] = 0.0f;
#pragma unroll
        for (int n = 0; n < 4; ++n) acc2[m][n] = 0.0f;
    }

    __syncthreads();

    for (int kt = 0; kt <= qTile; ++kt) {
        int kcol0 = kt * 128;
#pragma unroll
        for (int i = 0; i < 8; ++i) {
            int lin = tid + i * 256;
            int c = lin & 127, c4 = lin >> 7;
            float4 a = *(const float4*)&Kg[(size_t)(kcol0 + c) * Ec + c4 * 4];
            Ks[(c4 * 4 + 0) * 128 + c] = a.x;
            Ks[(c4 * 4 + 1) * 128 + c] = a.y;
            Ks[(c4 * 4 + 2) * 128 + c] = a.z;
            Ks[(c4 * 4 + 3) * 128 + c] = a.w;
        }
#pragma unroll
        for (int i = 0; i < 8; ++i) {
            int lin = tid + i * 256;
            int c = lin >> 4, d4 = lin & 15;
            *(float4*)&Vs[c * 64 + d4 * 4] =
                *(const float4*)&Vg[(size_t)(kcol0 + c) * Ec + d4 * 4];
        }
        __syncthreads();

        float acc[8][8];
#pragma unroll
        for (int m = 0; m < 8; ++m)
#pragma unroll
            for (int n = 0; n < 8; ++n) acc[m][n] = 0.0f;
#pragma unroll 4
        for (int kk = 0; kk < 64; ++kk) {
            float ra[8], rb[8];
            *(float4*)&ra[0] = *(float4*)&Qs[kk * 128 + ty * 8];
            *(float4*)&ra[4] = *(float4*)&Qs[kk * 128 + ty * 8 + 4];
            *(float4*)&rb[0] = *(float4*)&Ks[kk * 128 + tx * 8];
            *(float4*)&rb[4] = *(float4*)&Ks[kk * 128 + tx * 8 + 4];
#pragma unroll
            for (int m = 0; m < 8; ++m)
#pragma unroll
                for (int n = 0; n < 8; ++n) acc[m][n] += ra[m] * rb[n];
        }

#pragma unroll
        for (int m = 0; m < 8; ++m) {
            int q = qRow0 + ty * 8 + m;
            int kbase = kcol0 + tx * 8;
            float Rm = expf((float)(q - kbase) * decay) * invn[m];
            float vals[8];
            float ls = 0.0f;
#pragma unroll
            for (int n = 0; n < 8; ++n) {
                float v = 0.0f;
                if (kbase + n <= q) v = acc[m][n] * (Rm * pwneg[n]);
                vals[n] = v;
                ls += fabsf(v);
            }
#pragma unroll
            for (int off = 1; off < 16; off <<= 1)
                ls += __shfl_xor_sync(0xffffffffu, ls, off, 16);
            rowsum[m] += ls;
            *(float4*)&Ss[(ty * 8 + m) * 132 + tx * 8]     = *(float4*)&vals[0];
            *(float4*)&Ss[(ty * 8 + m) * 132 + tx * 8 + 4] = *(float4*)&vals[4];
        }
        __syncthreads();

#pragma unroll 4
        for (int kc = 0; kc < 128; ++kc) {
            float rb[4];
            *(float4*)&rb[0] = *(float4*)&Vs[kc * 64 + tx * 4];
#pragma unroll
            for (int m = 0; m < 8; ++m) {
                float ra = Ss[(ty * 8 + m) * 132 + kc];
#pragma unroll
                for (int n = 0; n < 4; ++n) acc2[m][n] += ra * rb[n];
            }
        }
        __syncthreads();
    }

#pragma unroll
    for (int m = 0; m < 8; ++m) {
        int q = qRow0 + ty * 8 + m;
        float den = fminf(fmaxf(rowsum[m], 1.0f), 50000.0f);
        float inv = 1.0f / den;
        float4 o;
        o.x = acc2[m][0] * inv; o.y = acc2[m][1] * inv;
        o.z = acc2[m][2] * inv; o.w = acc2[m][3] * inv;
        *(float4*)&g_av[(size_t)(b * Sc + q) * Ec + h * Dc + tx * 4] = o;
    }
}

// ---------------- RMSNorm over D, silu(g) gate, write output ----------------
__global__ void k_final(float* __restrict__ out) {
    __shared__ float warpsum[2];
    int bsh = blockIdx.x;
    int h = bsh & (Hc - 1);
    int bs = bsh >> 4;
    int d = threadIdx.x;
    size_t idx = (size_t)bs * Ec + h * Dc + d;
    float v = g_av[idx];
    float sq = v * v;
#pragma unroll
    for (int off = 16; off; off >>= 1) sq += __shfl_down_sync(0xffffffffu, sq, off);
    if ((d & 31) == 0) warpsum[d >> 5] = sq;
    __syncthreads();
    float total = warpsum[0] + warpsum[1];
    float scl = rsqrtf(total * (1.0f / 64.0f) + 1e-6f);
    float gg = g_g[idx];
    float silu = gg / (1.0f + expf(-gg));
    out[idx] = silu * v * scl;
}

// ---------------- launch ----------------
extern "C" void kernel_launch(void* const* d_in, const int* in_sizes, int n_in,
                              void* d_out, int out_size) {
    const float* x  = (const float*)d_in[0];
    const float* Wq = (const float*)d_in[1];
    const float* Wk = (const float*)d_in[2];
    const float* Wv = (const float*)d_in[3];
    const float* Wg = (const float*)d_in[4];
    float* out = (float*)d_out;

    cudaFuncSetAttribute(k_retention, cudaFuncAttributeMaxDynamicSharedMemorySize, SM_BYTES);

    k_sincos<<<(Sc * Dc + 255) / 256, 256>>>();
    k_norm<<<Hc, 256>>>();

    k_split_x<<<BSc * Ec / 256, 256>>>(x);
    k_split_w<<<dim3(Ec / 32, Ec / 32, 4), dim3(32, 8)>>>(Wq, Wk, Wv, Wg);

    k_gemm_mma<<<dim3(Ec / 128, BSc / 128, 4), 256>>>();

    k_theta<<<(BSc * Ec / 2 + 255) / 256, 256>>>();

    k_retention<<<dim3(1, Sc / 128, Bc * Hc), 256, SM_BYTES>>>();

    k_final<<<Bc * Sc * Hc, Dc>>>(out);
}

// round 13
// speedup vs baseline: 1.8896x; 1.4372x over previous
#include <cuda_runtime.h>
#include <cuda_bf16.h>
#include <math.h>
#include <stdint.h>

#define Bc 2
#define Sc 2048
#define Ec 1024
#define Hc 16
#define Dc 64
#define BSc (Bc*Sc)

// ---------------- scratch (device globals: allocation-free) ----------------
__device__ __align__(128) float g_q[BSc*Ec];
__device__ __align__(128) float g_k[BSc*Ec];
__device__ __align__(128) float g_v[BSc*Ec];
__device__ __align__(128) float g_g[BSc*Ec];
__device__ __align__(128) float g_av[BSc*Ec];
__device__ __align__(128) float g_sin[Sc*Dc];
__device__ __align__(128) float g_cos[Sc*Dc];
__device__ __align__(128) float g_invnorm[Hc*Sc];
__device__ __align__(128) __nv_bfloat16 g_xh[BSc*Ec];
__device__ __align__(128) __nv_bfloat16 g_xl[BSc*Ec];
__device__ __align__(128) __nv_bfloat16 g_wh[4*Ec*Ec];   // [z][n][k]
__device__ __align__(128) __nv_bfloat16 g_wl[4*Ec*Ec];
// per-head split operands for retention
__device__ __align__(128) __nv_bfloat16 g_qh[BSc*Ec];    // [bh][s][d]
__device__ __align__(128) __nv_bfloat16 g_ql[BSc*Ec];
__device__ __align__(128) __nv_bfloat16 g_kh[BSc*Ec];
__device__ __align__(128) __nv_bfloat16 g_kl[BSc*Ec];
__device__ __align__(128) __nv_bfloat16 g_vth[BSc*Ec];   // [bh][d][s] (transposed)
__device__ __align__(128) __nv_bfloat16 g_vtl[BSc*Ec];

// ---------------- warp-mma helpers (baseline PTX: sm_80+) ----------------
__device__ __forceinline__ uint32_t smem_u32(const void* p) {
    uint32_t a;
    asm("{ .reg .u64 t; cvta.to.shared.u64 t, %1; cvt.u32.u64 %0, t; }" : "=r"(a) : "l"(p));
    return a;
}
__device__ __forceinline__ void ldsm_x4(uint32_t& r0, uint32_t& r1, uint32_t& r2, uint32_t& r3,
                                        uint32_t addr) {
    asm volatile("ldmatrix.sync.aligned.m8n8.x4.shared.b16 {%0,%1,%2,%3}, [%4];"
                 : "=r"(r0), "=r"(r1), "=r"(r2), "=r"(r3) : "r"(addr));
}
__device__ __forceinline__ void mma_bf16(float* d, uint32_t a0, uint32_t a1, uint32_t a2,
                                         uint32_t a3, uint32_t b0, uint32_t b1) {
    asm volatile("mma.sync.aligned.m16n8k16.row.col.f32.bf16.bf16.f32 "
                 "{%0,%1,%2,%3}, {%4,%5,%6,%7}, {%8,%9}, {%0,%1,%2,%3};"
                 : "+f"(d[0]), "+f"(d[1]), "+f"(d[2]), "+f"(d[3])
                 : "r"(a0), "r"(a1), "r"(a2), "r"(a3), "r"(b0), "r"(b1));
}
__device__ __forceinline__ uint32_t packbf(float lo, float hi) {
    uint32_t r;
    asm("cvt.rn.bf16x2.f32 %0, %1, %2;" : "=r"(r) : "f"(hi), "f"(lo));
    return r;
}

// ---------------- precompute: sin/cos tables ----------------
__global__ void k_sincos() {
    int i = blockIdx.x * blockDim.x + threadIdx.x;
    if (i >= Sc * Dc) return;
    int s = i / Dc, d = i % Dc;
    float a = powf(10000.0f, -(float)(d >> 1) / (float)(Dc / 2 - 1));
    float ang = (float)s * a;
    g_sin[i] = sinf(ang);
    g_cos[i] = cosf(ang);
}

// ---------------- precompute: mask row normalizers ----------------
__global__ void k_norm() {
    int h = blockIdx.x;
    float r = 1.0f - exp2f(-(float)(5 + h));
    for (int q = threadIdx.x; q < Sc; q += blockDim.x) {
        float sum = 0.0f, p = 1.0f;
        for (int j = 0; j <= q; ++j) { sum += p; p *= r; }
        g_invnorm[h * Sc + q] = rsqrtf(sum);
    }
}

// ---------------- split X into bf16 hi/lo ----------------
__global__ void k_split_x(const float* __restrict__ X) {
    int i = blockIdx.x * 256 + threadIdx.x;
    float x = X[i];
    __nv_bfloat16 h = __float2bfloat16(x);
    g_xh[i] = h;
    g_xl[i] = __float2bfloat16(x - __bfloat162float(h));
}

// ---------------- transpose + split weights [n][k] ----------------
__global__ void k_split_w(const float* __restrict__ Wq, const float* __restrict__ Wk,
                          const float* __restrict__ Wv, const float* __restrict__ Wg) {
    __shared__ float t[32][33];
    int z = blockIdx.z;
    const float* W = (z == 0) ? Wq : (z == 1) ? Wk : (z == 2) ? Wv : Wg;
    int n0 = blockIdx.x * 32, k0 = blockIdx.y * 32;
    int tx = threadIdx.x, ty = threadIdx.y;   // 32 x 8
#pragma unroll
    for (int i = 0; i < 4; ++i)
        t[ty + i * 8][tx] = W[(size_t)(k0 + ty + i * 8) * Ec + n0 + tx];
    __syncthreads();
    size_t base = (size_t)z * Ec * Ec;
#pragma unroll
    for (int i = 0; i < 4; ++i) {
        float x = t[tx][ty + i * 8];
        __nv_bfloat16 h = __float2bfloat16(x);
        size_t idx = base + (size_t)(n0 + ty + i * 8) * Ec + k0 + tx;
        g_wh[idx] = h;
        g_wl[idx] = __float2bfloat16(x - __bfloat162float(h));
    }
}

// ---------------- projections via mma.sync ----------------
#define KCH 32
#define LDSW 40
#define NCHUNK 96

__global__ __launch_bounds__(256) void k_gemm_mma() {
    __shared__ __nv_bfloat16 smA[2][128 * LDSW];
    __shared__ __nv_bfloat16 smB[2][128 * LDSW];

    const int tid = threadIdx.x;
    const int wid = tid >> 5, lane = tid & 31;
    const int z = blockIdx.z;
    const int rowBase = blockIdx.y * 128;
    const int colBase = blockIdx.x * 128;

    const __nv_bfloat16* Wh = g_wh + (size_t)z * Ec * Ec;
    const __nv_bfloat16* Wl = g_wl + (size_t)z * Ec * Ec;
    float* O = (z == 0) ? g_q : (z == 1) ? g_k : (z == 2) ? g_v : g_g;
    const float scale = (z == 1) ? 0.03125f : 1.0f;

    const int warpM = wid & 3;
    const int warpN = wid >> 2;

    float acc[2][8][4];
#pragma unroll
    for (int mi = 0; mi < 2; ++mi)
#pragma unroll
        for (int nj = 0; nj < 8; ++nj)
#pragma unroll
            for (int e = 0; e < 4; ++e) acc[mi][nj][e] = 0.0f;

    const int lt = lane >> 3, lr = lane & 7;
    const int ldsmRow = (lt & 1) * 8 + lr;
    const int ldsmKB  = (lt >> 1) * 16;
    uint32_t baseA = smem_u32(&smA[0][0]);
    uint32_t baseB = smem_u32(&smB[0][0]);
    const uint32_t BUFB = 128 * LDSW * 2;

    const int l0 = tid, l1 = tid + 256;
    const int l0r = l0 >> 2, l0i = l0 & 3;
    const int l1r = l1 >> 2, l1i = l1 & 3;

    {
        const __nv_bfloat16* Ag = g_xh + (size_t)rowBase * Ec;
        const __nv_bfloat16* Bg = Wh + (size_t)colBase * Ec;
        *(uint4*)((char*)&smA[0][0] + l0r * 80 + l0i * 16) = *(const uint4*)(Ag + (size_t)l0r * Ec + l0i * 8);
        *(uint4*)((char*)&smA[0][0] + l1r * 80 + l1i * 16) = *(const uint4*)(Ag + (size_t)l1r * Ec + l1i * 8);
        *(uint4*)((char*)&smB[0][0] + l0r * 80 + l0i * 16) = *(const uint4*)(Bg + (size_t)l0r * Ec + l0i * 8);
        *(uint4*)((char*)&smB[0][0] + l1r * 80 + l1i * 16) = *(const uint4*)(Bg + (size_t)l1r * Ec + l1i * 8);
    }
    __syncthreads();

    for (int c = 0; c < NCHUNK; ++c) {
        int buf = c & 1;
        uint4 tA0, tA1, tB0, tB1;
        bool hasNext = (c + 1 < NCHUNK);
        if (hasNext) {
            int cn = c + 1;
            int blk = cn >> 5;
            int kk0 = (cn & 31) * KCH;
            const __nv_bfloat16* Ag = ((blk < 2) ? g_xh : g_xl) + (size_t)rowBase * Ec + kk0;
            const __nv_bfloat16* Bg = ((blk == 1) ? Wl : Wh) + (size_t)colBase * Ec + kk0;
            tA0 = *(const uint4*)(Ag + (size_t)l0r * Ec + l0i * 8);
            tA1 = *(const uint4*)(Ag + (size_t)l1r * Ec + l1i * 8);
            tB0 = *(const uint4*)(Bg + (size_t)l0r * Ec + l0i * 8);
            tB1 = *(const uint4*)(Bg + (size_t)l1r * Ec + l1i * 8);
        }

        uint32_t bufA = baseA + buf * BUFB;
        uint32_t bufB = baseB + buf * BUFB;
#pragma unroll
        for (int s = 0; s < 2; ++s) {
            int kB = s * 32 + ldsmKB;
            uint32_t a[2][4];
#pragma unroll
            for (int mi = 0; mi < 2; ++mi) {
                uint32_t addr = bufA + (warpM * 32 + mi * 16 + ldsmRow) * 80 + kB;
                ldsm_x4(a[mi][0], a[mi][1], a[mi][2], a[mi][3], addr);
            }
            uint32_t bt[4][4];
#pragma unroll
            for (int ni = 0; ni < 4; ++ni) {
                uint32_t addr = bufB + (warpN * 64 + ni * 16 + ldsmRow) * 80 + kB;
                ldsm_x4(bt[ni][0], bt[ni][1], bt[ni][2], bt[ni][3], addr);
            }
#pragma unroll
            for (int mi = 0; mi < 2; ++mi)
#pragma unroll
                for (int ni = 0; ni < 4; ++ni) {
                    mma_bf16(acc[mi][ni * 2 + 0], a[mi][0], a[mi][1], a[mi][2], a[mi][3],
                             bt[ni][0], bt[ni][2]);
                    mma_bf16(acc[mi][ni * 2 + 1], a[mi][0], a[mi][1], a[mi][2], a[mi][3],
                             bt[ni][1], bt[ni][3]);
                }
        }

        if (hasNext) {
            int nb = buf ^ 1;
            *(uint4*)((char*)&smA[nb][0] + l0r * 80 + l0i * 16) = tA0;
            *(uint4*)((char*)&smA[nb][0] + l1r * 80 + l1i * 16) = tA1;
            *(uint4*)((char*)&smB[nb][0] + l0r * 80 + l0i * 16) = tB0;
            *(uint4*)((char*)&smB[nb][0] + l1r * 80 + l1i * 16) = tB1;
        }
        __syncthreads();
    }

    const int mrow = rowBase + warpM * 32 + (lane >> 2);
    const int mcol = colBase + warpN * 64 + (lane & 3) * 2;
#pragma unroll
    for (int mi = 0; mi < 2; ++mi)
#pragma unroll
        for (int nj = 0; nj < 8; ++nj) {
            int r0 = mrow + mi * 16;
            int c0 = mcol + nj * 8;
            float2 v0 = { acc[mi][nj][0] * scale, acc[mi][nj][1] * scale };
            float2 v1 = { acc[mi][nj][2] * scale, acc[mi][nj][3] * scale };
            *(float2*)&O[(size_t)r0 * Ec + c0]       = v0;
            *(float2*)&O[(size_t)(r0 + 8) * Ec + c0] = v1;
        }
}

// ---------------- rotary + split q,k into per-head bf16 hi/lo ----------------
__global__ void k_theta_split() {
    int i = blockIdx.x * blockDim.x + threadIdx.x;
    if (i >= BSc * Ec / 2) return;
    int e2 = i % (Ec / 2);
    int bs = i / (Ec / 2);
    int e = e2 * 2;
    int h = e >> 6;
    int d = e & 63;
    int s = bs % Sc;
    int b = bs / Sc;
    float sn0 = g_sin[s * Dc + d], sn1 = g_sin[s * Dc + d + 1];
    float cs0 = g_cos[s * Dc + d], cs1 = g_cos[s * Dc + d + 1];
    size_t src = (size_t)bs * Ec + e;
    float q0 = g_q[src], q1 = g_q[src + 1];
    float qr0 = q0 * cs0 - q1 * sn0;
    float qr1 = q1 * cs1 + q0 * sn1;
    float k0 = g_k[src], k1 = g_k[src + 1];
    float kr0 = k0 * cs0 - k1 * sn0;
    float kr1 = k1 * cs1 + k0 * sn1;
    size_t dst = ((size_t)(b * Hc + h) * Sc + s) * Dc + d;
    __nv_bfloat16 a0 = __float2bfloat16(qr0), a1 = __float2bfloat16(qr1);
    *(__nv_bfloat162*)&g_qh[dst] = __nv_bfloat162(a0, a1);
    *(__nv_bfloat162*)&g_ql[dst] = __nv_bfloat162(
        __float2bfloat16(qr0 - __bfloat162float(a0)),
        __float2bfloat16(qr1 - __bfloat162float(a1)));
    __nv_bfloat16 c0 = __float2bfloat16(kr0), c1 = __float2bfloat16(kr1);
    *(__nv_bfloat162*)&g_kh[dst] = __nv_bfloat162(c0, c1);
    *(__nv_bfloat162*)&g_kl[dst] = __nv_bfloat162(
        __float2bfloat16(kr0 - __bfloat162float(c0)),
        __float2bfloat16(kr1 - __bfloat162float(c1)));
}

// ---------------- transpose + split V into [bh][d][s] bf16 hi/lo ----------------
__global__ void k_v_split_t() {
    __shared__ float t[32][33];
    int bh = blockIdx.z;
    int b = bh >> 4, h = bh & 15;
    int s0 = blockIdx.x * 32, d0 = blockIdx.y * 32;
    int tx = threadIdx.x, ty = threadIdx.y;   // 32 x 8
#pragma unroll
    for (int i = 0; i < 4; ++i)
        t[ty + i * 8][tx] = g_v[(size_t)(b * Sc + s0 + ty + i * 8) * Ec + h * 64 + d0 + tx];
    __syncthreads();
#pragma unroll
    for (int i = 0; i < 4; ++i) {
        float x = t[tx][ty + i * 8];   // (s = s0+tx, d = d0+ty+i*8)
        __nv_bfloat16 hi = __float2bfloat16(x);
        size_t dst = (size_t)bh * Dc * Sc + (size_t)(d0 + ty + i * 8) * Sc + s0 + tx;
        g_vth[dst] = hi;
        g_vtl[dst] = __float2bfloat16(x - __bfloat162float(hi));
    }
}

// ---------------- fused retention via mma.sync (flash-style, split-bf16) ----------------
#define QK_STR 144     // 72 bf16 per row
#define VT_STR 272     // 136 bf16 per row
#define OQH 0
#define OQL 18432
#define OKH 36864
#define OKL 55296
#define OVH 73728
#define OVL 91136
#define ORS 108544     // rowsum: 2 x 128 floats
#define RSM_BYTES (ORS + 1024)

__global__ __launch_bounds__(256) void k_ret_mma() {
    extern __shared__ char smc[];
    uint32_t smb = smem_u32(smc);
    const int tid = threadIdx.x, wid = tid >> 5, lane = tid & 31;
    const int warpM = wid & 3, warpN = wid >> 2;
    const int bh = blockIdx.z;
    const int b = bh >> 4, h = bh & 15;
    const int qTile = 15 - (int)blockIdx.y;     // heavy first
    const int qRow0 = qTile * 128;
    const int lt = lane >> 3, lr = lane & 7;
    const int ldRow = (lt & 1) * 8 + lr;
    const int ldKB = (lt >> 1) * 16;
    const int r0 = lane >> 2;
    const int c2 = (lane & 3) * 2;

    const __nv_bfloat16* Qh = g_qh + (size_t)bh * Sc * Dc;
    const __nv_bfloat16* Ql = g_ql + (size_t)bh * Sc * Dc;
    const __nv_bfloat16* Kh = g_kh + (size_t)bh * Sc * Dc;
    const __nv_bfloat16* Kl = g_kl + (size_t)bh * Sc * Dc;
    const __nv_bfloat16* Vh = g_vth + (size_t)bh * Dc * Sc;
    const __nv_bfloat16* Vl = g_vtl + (size_t)bh * Dc * Sc;

    // load Q tiles once
#pragma unroll
    for (int i = 0; i < 4; ++i) {
        int s = tid + i * 256;
        int r = s >> 3, i8 = s & 7;
        *(uint4*)(smc + OQH + r * QK_STR + i8 * 16) =
            *(const uint4*)(Qh + (size_t)(qRow0 + r) * Dc + i8 * 8);
        *(uint4*)(smc + OQL + r * QK_STR + i8 * 16) =
            *(const uint4*)(Ql + (size_t)(qRow0 + r) * Dc + i8 * 8);
    }

    const float decay = logf(1.0f - exp2f(-(float)(5 + h)));
    float rowf[4];
#pragma unroll
    for (int i = 0; i < 4; ++i) {
        int row = warpM * 32 + (i >> 1) * 16 + (i & 1) * 8 + r0;
        int q = qRow0 + row;
        rowf[i] = expf((float)q * decay) * g_invnorm[h * Sc + q];
    }
    float colf[16];
#pragma unroll
    for (int nj = 0; nj < 8; ++nj)
#pragma unroll
        for (int e = 0; e < 2; ++e) {
            int cloc = warpN * 64 + nj * 8 + c2 + e;
            colf[nj * 2 + e] = expf(-(float)cloc * decay);
        }

    float acc2[2][8][4];
#pragma unroll
    for (int mi = 0; mi < 2; ++mi)
#pragma unroll
        for (int nj = 0; nj < 8; ++nj)
#pragma unroll
            for (int e = 0; e < 4; ++e) acc2[mi][nj][e] = 0.0f;
    float rsum[4] = {0.f, 0.f, 0.f, 0.f};

    __syncthreads();

    for (int kt = 0; kt <= qTile; ++kt) {
        const int kcol0 = kt * 128;
#pragma unroll
        for (int i = 0; i < 4; ++i) {
            int s = tid + i * 256;
            int r = s >> 3, i8 = s & 7;
            *(uint4*)(smc + OKH + r * QK_STR + i8 * 16) =
                *(const uint4*)(Kh + (size_t)(kcol0 + r) * Dc + i8 * 8);
            *(uint4*)(smc + OKL + r * QK_STR + i8 * 16) =
                *(const uint4*)(Kl + (size_t)(kcol0 + r) * Dc + i8 * 8);
        }
#pragma unroll
        for (int i = 0; i < 4; ++i) {
            int s = tid + i * 256;
            int r = s >> 4, i16 = s & 15;
            *(uint4*)(smc + OVH + r * VT_STR + i16 * 16) =
                *(const uint4*)(Vh + (size_t)r * Sc + kcol0 + i16 * 8);
            *(uint4*)(smc + OVL + r * VT_STR + i16 * 16) =
                *(const uint4*)(Vl + (size_t)r * Sc + kcol0 + i16 * 8);
        }
        __syncthreads();

        // ---- GEMM1: S = Q K^T (3 split terms) ----
        float acc[2][8][4];
#pragma unroll
        for (int mi = 0; mi < 2; ++mi)
#pragma unroll
            for (int nj = 0; nj < 8; ++nj)
#pragma unroll
                for (int e = 0; e < 4; ++e) acc[mi][nj][e] = 0.0f;
#pragma unroll
        for (int t = 0; t < 3; ++t) {
            uint32_t abase = smb + ((t < 2) ? OQH : OQL);
            uint32_t bbase = smb + ((t == 1) ? OKL : OKH);
#pragma unroll
            for (int s = 0; s < 4; ++s) {
                uint32_t a[2][4];
#pragma unroll
                for (int mi = 0; mi < 2; ++mi)
                    ldsm_x4(a[mi][0], a[mi][1], a[mi][2], a[mi][3],
                            abase + (warpM * 32 + mi * 16 + ldRow) * QK_STR + s * 32 + ldKB);
                uint32_t bt[4][4];
#pragma unroll
                for (int ng = 0; ng < 4; ++ng)
                    ldsm_x4(bt[ng][0], bt[ng][1], bt[ng][2], bt[ng][3],
                            bbase + (warpN * 64 + ng * 16 + ldRow) * QK_STR + s * 32 + ldKB);
#pragma unroll
                for (int mi = 0; mi < 2; ++mi)
#pragma unroll
                    for (int ng = 0; ng < 4; ++ng) {
                        mma_bf16(acc[mi][ng * 2 + 0], a[mi][0], a[mi][1], a[mi][2], a[mi][3],
                                 bt[ng][0], bt[ng][2]);
                        mma_bf16(acc[mi][ng * 2 + 1], a[mi][0], a[mi][1], a[mi][2], a[mi][3],
                                 bt[ng][1], bt[ng][3]);
                    }
            }
        }

        // ---- mask + rowsum + convert + GEMM2 per k16 slice ----
        const float ektf = expf(-(float)kcol0 * decay);
        const bool diag = (kt == qTile);
        float rk[4];
#pragma unroll
        for (int i = 0; i < 4; ++i) rk[i] = rowf[i] * ektf;

#pragma unroll
        for (int s = 0; s < 4; ++s) {
            uint32_t shA[2][4], slA[2][4];
#pragma unroll
            for (int mi = 0; mi < 2; ++mi) {
                float sv[2][4];
#pragma unroll
                for (int p = 0; p < 2; ++p) {
                    int nj = 2 * s + p;
#pragma unroll
                    for (int e = 0; e < 4; ++e) {
                        int half = e >> 1;
                        float v = acc[mi][nj][e] * (rk[mi * 2 + half] * colf[nj * 2 + (e & 1)]);
                        if (diag) {
                            int rowl = warpM * 32 + mi * 16 + half * 8 + r0;
                            int cloc = warpN * 64 + nj * 8 + c2 + (e & 1);
                            if (cloc > rowl) v = 0.0f;
                        }
                        sv[p][e] = v;
                        rsum[mi * 2 + half] += fabsf(v);
                    }
                }
                float sh[2][4], sl[2][4];
#pragma unroll
                for (int p = 0; p < 2; ++p)
#pragma unroll
                    for (int e = 0; e < 4; ++e) {
                        sh[p][e] = __bfloat162float(__float2bfloat16(sv[p][e]));
                        sl[p][e] = sv[p][e] - sh[p][e];
                    }
                shA[mi][0] = packbf(sh[0][0], sh[0][1]);
                shA[mi][1] = packbf(sh[0][2], sh[0][3]);
                shA[mi][2] = packbf(sh[1][0], sh[1][1]);
                shA[mi][3] = packbf(sh[1][2], sh[1][3]);
                slA[mi][0] = packbf(sl[0][0], sl[0][1]);
                slA[mi][1] = packbf(sl[0][2], sl[0][3]);
                slA[mi][2] = packbf(sl[1][0], sl[1][1]);
                slA[mi][3] = packbf(sl[1][2], sl[1][3]);
            }
            // V fragments: this warp's S columns are keys [kcol0 + warpN*64 + 16s, +16)
            // => V smem element offset warpN*64 + 16s (bytes: warpN*128 + s*32)
            uint32_t vh[4][4], vl[4][4];
#pragma unroll
            for (int ng = 0; ng < 4; ++ng) {
                ldsm_x4(vh[ng][0], vh[ng][1], vh[ng][2], vh[ng][3],
                        smb + OVH + (ng * 16 + ldRow) * VT_STR + warpN * 128 + s * 32 + ldKB);
                ldsm_x4(vl[ng][0], vl[ng][1], vl[ng][2], vl[ng][3],
                        smb + OVL + (ng * 16 + ldRow) * VT_STR + warpN * 128 + s * 32 + ldKB);
            }
#pragma unroll
            for (int mi = 0; mi < 2; ++mi)
#pragma unroll
                for (int ng = 0; ng < 4; ++ng) {
                    mma_bf16(acc2[mi][ng * 2 + 0], shA[mi][0], shA[mi][1], shA[mi][2], shA[mi][3],
                             vh[ng][0], vh[ng][2]);
                    mma_bf16(acc2[mi][ng * 2 + 1], shA[mi][0], shA[mi][1], shA[mi][2], shA[mi][3],
                             vh[ng][1], vh[ng][3]);
                    mma_bf16(acc2[mi][ng * 2 + 0], slA[mi][0], slA[mi][1], slA[mi][2], slA[mi][3],
                             vh[ng][0], vh[ng][2]);
                    mma_bf16(acc2[mi][ng * 2 + 1], slA[mi][0], slA[mi][1], slA[mi][2], slA[mi][3],
                             vh[ng][1], vh[ng][3]);
                    mma_bf16(acc2[mi][ng * 2 + 0], shA[mi][0], shA[mi][1], shA[mi][2], shA[mi][3],
                             vl[ng][0], vl[ng][2]);
                    mma_bf16(acc2[mi][ng * 2 + 1], shA[mi][0], shA[mi][1], shA[mi][2], shA[mi][3],
                             vl[ng][1], vl[ng][3]);
                }
        }
        __syncthreads();
    }

    // ---- epilogue ----
    float* RS = (float*)(smc + ORS);
#pragma unroll
    for (int i = 0; i < 4; ++i) {
        float v = rsum[i];
        v += __shfl_xor_sync(0xffffffffu, v, 1);
        v += __shfl_xor_sync(0xffffffffu, v, 2);
        rsum[i] = v;
    }
    if ((lane & 3) == 0) {
#pragma unroll
        for (int i = 0; i < 4; ++i)
            RS[warpN * 128 + warpM * 32 + (i >> 1) * 16 + (i & 1) * 8 + r0] = rsum[i];
    }
    __syncthreads();

    float* accS = (float*)smc;   // reuse Q region (dead after kt loop)
    if (warpN == 1) {
#pragma unroll
        for (int mi = 0; mi < 2; ++mi)
#pragma unroll
            for (int nj = 0; nj < 8; ++nj) {
                int rowl = warpM * 32 + mi * 16 + r0;
                *(float2*)&accS[(size_t)rowl * 64 + nj * 8 + c2] =
                    make_float2(acc2[mi][nj][0], acc2[mi][nj][1]);
                *(float2*)&accS[(size_t)(rowl + 8) * 64 + nj * 8 + c2] =
                    make_float2(acc2[mi][nj][2], acc2[mi][nj][3]);
            }
    }
    __syncthreads();
    if (warpN == 0) {
#pragma unroll
        for (int mi = 0; mi < 2; ++mi) {
            int rowl = warpM * 32 + mi * 16 + r0;
            float d0 = RS[rowl] + RS[128 + rowl];
            float d1 = RS[rowl + 8] + RS[128 + rowl + 8];
            float inv0 = 1.0f / fminf(fmaxf(d0, 1.0f), 50000.0f);
            float inv1 = 1.0f / fminf(fmaxf(d1, 1.0f), 50000.0f);
#pragma unroll
            for (int nj = 0; nj < 8; ++nj) {
                float2 p0 = *(float2*)&accS[(size_t)rowl * 64 + nj * 8 + c2];
                float2 p1 = *(float2*)&accS[(size_t)(rowl + 8) * 64 + nj * 8 + c2];
                float2 o0 = make_float2((acc2[mi][nj][0] + p0.x) * inv0,
                                        (acc2[mi][nj][1] + p0.y) * inv0);
                float2 o1 = make_float2((acc2[mi][nj][2] + p1.x) * inv1,
                                        (acc2[mi][nj][3] + p1.y) * inv1);
                int col = nj * 8 + c2;
                *(float2*)&g_av[(size_t)(b * Sc + qRow0 + rowl) * Ec + h * 64 + col] = o0;
                *(float2*)&g_av[(size_t)(b * Sc + qRow0 + rowl + 8) * Ec + h * 64 + col] = o1;
            }
        }
    }
}

// ---------------- RMSNorm over D, silu(g) gate, write output ----------------
__global__ void k_final(float* __restrict__ out) {
    __shared__ float warpsum[2];
    int bsh = blockIdx.x;
    int h = bsh & (Hc - 1);
    int bs = bsh >> 4;
    int d = threadIdx.x;
    size_t idx = (size_t)bs * Ec + h * Dc + d;
    float v = g_av[idx];
    float sq = v * v;
#pragma unroll
    for (int off = 16; off; off >>= 1) sq += __shfl_down_sync(0xffffffffu, sq, off);
    if ((d & 31) == 0) warpsum[d >> 5] = sq;
    __syncthreads();
    float total = warpsum[0] + warpsum[1];
    float scl = rsqrtf(total * (1.0f / 64.0f) + 1e-6f);
    float gg = g_g[idx];
    float silu = gg / (1.0f + expf(-gg));
    out[idx] = silu * v * scl;
}

// ---------------- launch ----------------
extern "C" void kernel_launch(void* const* d_in, const int* in_sizes, int n_in,
                              void* d_out, int out_size) {
    const float* x  = (const float*)d_in[0];
    const float* Wq = (const float*)d_in[1];
    const float* Wk = (const float*)d_in[2];
    const float* Wv = (const float*)d_in[3];
    const float* Wg = (const float*)d_in[4];
    float* out = (float*)d_out;

    cudaFuncSetAttribute(k_ret_mma, cudaFuncAttributeMaxDynamicSharedMemorySize, RSM_BYTES);

    k_sincos<<<(Sc * Dc + 255) / 256, 256>>>();
    k_norm<<<Hc, 256>>>();

    k_split_x<<<BSc * Ec / 256, 256>>>(x);
    k_split_w<<<dim3(Ec / 32, Ec / 32, 4), dim3(32, 8)>>>(Wq, Wk, Wv, Wg);

    k_gemm_mma<<<dim3(Ec / 128, BSc / 128, 4), 256>>>();

    k_theta_split<<<(BSc * Ec / 2 + 255) / 256, 256>>>();
    k_v_split_t<<<dim3(Sc / 32, Dc / 32, Bc * Hc), dim3(32, 8)>>>();

    k_ret_mma<<<dim3(1, 16, Bc * Hc), 256, RSM_BYTES>>>();

    k_final<<<Bc * Sc * Hc, Dc>>>(out);
}

// round 15
// speedup vs baseline: 2.3896x; 1.2646x over previous
#include <cuda_runtime.h>
#include <cuda_bf16.h>
#include <cuda_fp16.h>
#include <math.h>
#include <stdint.h>

#define Bc 2
#define Sc 2048
#define Ec 1024
#define Hc 16
#define Dc 64
#define BSc (Bc*Sc)

// ---------------- scratch (device globals: allocation-free) ----------------
__device__ __align__(128) float g_q[BSc*Ec];
__device__ __align__(128) float g_k[BSc*Ec];
__device__ __align__(128) float g_v[BSc*Ec];
__device__ __align__(128) float g_g[BSc*Ec];
__device__ __align__(128) float g_av[BSc*Ec];
__device__ __align__(128) float g_sin[Sc*Dc];
__device__ __align__(128) float g_cos[Sc*Dc];
__device__ __align__(128) float g_invnorm[Hc*Sc];
__device__ __align__(128) __half g_xh[BSc*Ec];           // x in fp16 (single)
__device__ __align__(128) __half g_wh[4*Ec*Ec];          // [z][n][k] fp16 hi
__device__ __align__(128) __half g_wl[4*Ec*Ec];          // fp16 lo (W exact to 2^-22)
// per-head split operands for retention (QK path: bf16 2-term each)
__device__ __align__(128) __nv_bfloat16 g_qh[BSc*Ec];    // [bh][s][d]
__device__ __align__(128) __nv_bfloat16 g_ql[BSc*Ec];
__device__ __align__(128) __nv_bfloat16 g_kh[BSc*Ec];
__device__ __align__(128) __nv_bfloat16 g_kl[BSc*Ec];
__device__ __align__(128) __half g_vth[BSc*Ec];          // [bh][d][s] fp16 hi
__device__ __align__(128) __half g_vtl[BSc*Ec];          // fp16 lo (V exact to 2^-22)

// ---------------- warp-mma helpers (baseline PTX: sm_80+) ----------------
__device__ __forceinline__ uint32_t smem_u32(const void* p) {
    uint32_t a;
    asm("{ .reg .u64 t; cvta.to.shared.u64 t, %1; cvt.u32.u64 %0, t; }" : "=r"(a) : "l"(p));
    return a;
}
__device__ __forceinline__ void ldsm_x4(uint32_t& r0, uint32_t& r1, uint32_t& r2, uint32_t& r3,
                                        uint32_t addr) {
    asm volatile("ldmatrix.sync.aligned.m8n8.x4.shared.b16 {%0,%1,%2,%3}, [%4];"
                 : "=r"(r0), "=r"(r1), "=r"(r2), "=r"(r3) : "r"(addr));
}
__device__ __forceinline__ void mma_bf16(float* d, uint32_t a0, uint32_t a1, uint32_t a2,
                                         uint32_t a3, uint32_t b0, uint32_t b1) {
    asm volatile("mma.sync.aligned.m16n8k16.row.col.f32.bf16.bf16.f32 "
                 "{%0,%1,%2,%3}, {%4,%5,%6,%7}, {%8,%9}, {%0,%1,%2,%3};"
                 : "+f"(d[0]), "+f"(d[1]), "+f"(d[2]), "+f"(d[3])
                 : "r"(a0), "r"(a1), "r"(a2), "r"(a3), "r"(b0), "r"(b1));
}
__device__ __forceinline__ void mma_fp16(float* d, uint32_t a0, uint32_t a1, uint32_t a2,
                                         uint32_t a3, uint32_t b0, uint32_t b1) {
    asm volatile("mma.sync.aligned.m16n8k16.row.col.f32.f16.f16.f32 "
                 "{%0,%1,%2,%3}, {%4,%5,%6,%7}, {%8,%9}, {%0,%1,%2,%3};"
                 : "+f"(d[0]), "+f"(d[1]), "+f"(d[2]), "+f"(d[3])
                 : "r"(a0), "r"(a1), "r"(a2), "r"(a3), "r"(b0), "r"(b1));
}
__device__ __forceinline__ uint32_t packh(float lo, float hi) {
    uint32_t r;
    asm("cvt.rn.f16x2.f32 %0, %1, %2;" : "=r"(r) : "f"(hi), "f"(lo));
    return r;
}

// ---------------- precompute: sin/cos tables ----------------
__global__ void k_sincos() {
    int i = blockIdx.x * blockDim.x + threadIdx.x;
    if (i >= Sc * Dc) return;
    int s = i / Dc, d = i % Dc;
    float a = powf(10000.0f, -(float)(d >> 1) / (float)(Dc / 2 - 1));
    float ang = (float)s * a;
    g_sin[i] = sinf(ang);
    g_cos[i] = cosf(ang);
}

// ---------------- precompute: mask row normalizers ----------------
__global__ void k_norm() {
    int h = blockIdx.x;
    float r = 1.0f - exp2f(-(float)(5 + h));
    for (int q = threadIdx.x; q < Sc; q += blockDim.x) {
        float sum = 0.0f, p = 1.0f;
        for (int j = 0; j <= q; ++j) { sum += p; p *= r; }
        g_invnorm[h * Sc + q] = rsqrtf(sum);
    }
}

// ---------------- cast X to fp16 ----------------
__global__ void k_split_x(const float* __restrict__ X) {
    int i = blockIdx.x * 256 + threadIdx.x;
    g_xh[i] = __float2half(X[i]);
}

// ---------------- transpose + split weights [n][k] into fp16 hi/lo ----------------
__global__ void k_split_w(const float* __restrict__ Wq, const float* __restrict__ Wk,
                          const float* __restrict__ Wv, const float* __restrict__ Wg) {
    __shared__ float t[32][33];
    int z = blockIdx.z;
    const float* W = (z == 0) ? Wq : (z == 1) ? Wk : (z == 2) ? Wv : Wg;
    int n0 = blockIdx.x * 32, k0 = blockIdx.y * 32;
    int tx = threadIdx.x, ty = threadIdx.y;   // 32 x 8
#pragma unroll
    for (int i = 0; i < 4; ++i)
        t[ty + i * 8][tx] = W[(size_t)(k0 + ty + i * 8) * Ec + n0 + tx];
    __syncthreads();
    size_t base = (size_t)z * Ec * Ec;
#pragma unroll
    for (int i = 0; i < 4; ++i) {
        float x = t[tx][ty + i * 8];
        __half h = __float2half(x);
        size_t idx = base + (size_t)(n0 + ty + i * 8) * Ec + k0 + tx;
        g_wh[idx] = h;
        g_wl[idx] = __float2half(x - __half2float(h));
    }
}

// ---------------- projections via mma.sync (fp16, 2 terms: x*Wh + x*Wl) ----------------
#define KCH 32
#define LDSW 40
#define NCHUNK 64

__global__ __launch_bounds__(256) void k_gemm_mma() {
    __shared__ __half smA[2][128 * LDSW];
    __shared__ __half smB[2][128 * LDSW];

    const int tid = threadIdx.x;
    const int wid = tid >> 5, lane = tid & 31;
    const int z = blockIdx.z;
    const int rowBase = blockIdx.y * 128;
    const int colBase = blockIdx.x * 128;

    const __half* Wh = g_wh + (size_t)z * Ec * Ec;
    const __half* Wl = g_wl + (size_t)z * Ec * Ec;
    float* O = (z == 0) ? g_q : (z == 1) ? g_k : (z == 2) ? g_v : g_g;
    const float scale = (z == 1) ? 0.03125f : 1.0f;

    const int warpM = wid & 3;
    const int warpN = wid >> 2;

    float acc[2][8][4];
#pragma unroll
    for (int mi = 0; mi < 2; ++mi)
#pragma unroll
        for (int nj = 0; nj < 8; ++nj)
#pragma unroll
            for (int e = 0; e < 4; ++e) acc[mi][nj][e] = 0.0f;

    const int lt = lane >> 3, lr = lane & 7;
    const int ldsmRow = (lt & 1) * 8 + lr;
    const int ldsmKB  = (lt >> 1) * 16;
    uint32_t baseA = smem_u32(&smA[0][0]);
    uint32_t baseB = smem_u32(&smB[0][0]);
    const uint32_t BUFB = 128 * LDSW * 2;

    const int l0 = tid, l1 = tid + 256;
    const int l0r = l0 >> 2, l0i = l0 & 3;
    const int l1r = l1 >> 2, l1i = l1 & 3;

    {
        const __half* Ag = g_xh + (size_t)rowBase * Ec;
        const __half* Bg = Wh + (size_t)colBase * Ec;
        *(uint4*)((char*)&smA[0][0] + l0r * 80 + l0i * 16) = *(const uint4*)(Ag + (size_t)l0r * Ec + l0i * 8);
        *(uint4*)((char*)&smA[0][0] + l1r * 80 + l1i * 16) = *(const uint4*)(Ag + (size_t)l1r * Ec + l1i * 8);
        *(uint4*)((char*)&smB[0][0] + l0r * 80 + l0i * 16) = *(const uint4*)(Bg + (size_t)l0r * Ec + l0i * 8);
        *(uint4*)((char*)&smB[0][0] + l1r * 80 + l1i * 16) = *(const uint4*)(Bg + (size_t)l1r * Ec + l1i * 8);
    }
    __syncthreads();

    for (int c = 0; c < NCHUNK; ++c) {
        int buf = c & 1;
        uint4 tA0, tA1, tB0, tB1;
        bool hasNext = (c + 1 < NCHUNK);
        if (hasNext) {
            int cn = c + 1;
            int blk = cn >> 5;                 // 0: Wh, 1: Wl (A always xh)
            int kk0 = (cn & 31) * KCH;
            const __half* Ag = g_xh + (size_t)rowBase * Ec + kk0;
            const __half* Bg = (blk ? Wl : Wh) + (size_t)colBase * Ec + kk0;
            tA0 = *(const uint4*)(Ag + (size_t)l0r * Ec + l0i * 8);
            tA1 = *(const uint4*)(Ag + (size_t)l1r * Ec + l1i * 8);
            tB0 = *(const uint4*)(Bg + (size_t)l0r * Ec + l0i * 8);
            tB1 = *(const uint4*)(Bg + (size_t)l1r * Ec + l1i * 8);
        }

        uint32_t bufA = baseA + buf * BUFB;
        uint32_t bufB = baseB + buf * BUFB;
#pragma unroll
        for (int s = 0; s < 2; ++s) {
            int kB = s * 32 + ldsmKB;
            uint32_t a[2][4];
#pragma unroll
            for (int mi = 0; mi < 2; ++mi) {
                uint32_t addr = bufA + (warpM * 32 + mi * 16 + ldsmRow) * 80 + kB;
                ldsm_x4(a[mi][0], a[mi][1], a[mi][2], a[mi][3], addr);
            }
            uint32_t bt[4][4];
#pragma unroll
            for (int ni = 0; ni < 4; ++ni) {
                uint32_t addr = bufB + (warpN * 64 + ni * 16 + ldsmRow) * 80 + kB;
                ldsm_x4(bt[ni][0], bt[ni][1], bt[ni][2], bt[ni][3], addr);
            }
#pragma unroll
            for (int mi = 0; mi < 2; ++mi)
#pragma unroll
                for (int ni = 0; ni < 4; ++ni) {
                    mma_fp16(acc[mi][ni * 2 + 0], a[mi][0], a[mi][1], a[mi][2], a[mi][3],
                             bt[ni][0], bt[ni][2]);
                    mma_fp16(acc[mi][ni * 2 + 1], a[mi][0], a[mi][1], a[mi][2], a[mi][3],
                             bt[ni][1], bt[ni][3]);
                }
        }

        if (hasNext) {
            int nb = buf ^ 1;
            *(uint4*)((char*)&smA[nb][0] + l0r * 80 + l0i * 16) = tA0;
            *(uint4*)((char*)&smA[nb][0] + l1r * 80 + l1i * 16) = tA1;
            *(uint4*)((char*)&smB[nb][0] + l0r * 80 + l0i * 16) = tB0;
            *(uint4*)((char*)&smB[nb][0] + l1r * 80 + l1i * 16) = tB1;
        }
        __syncthreads();
    }

    const int mrow = rowBase + warpM * 32 + (lane >> 2);
    const int mcol = colBase + warpN * 64 + (lane & 3) * 2;
#pragma unroll
    for (int mi = 0; mi < 2; ++mi)
#pragma unroll
        for (int nj = 0; nj < 8; ++nj) {
            int r0 = mrow + mi * 16;
            int c0 = mcol + nj * 8;
            float2 v0 = { acc[mi][nj][0] * scale, acc[mi][nj][1] * scale };
            float2 v1 = { acc[mi][nj][2] * scale, acc[mi][nj][3] * scale };
            *(float2*)&O[(size_t)r0 * Ec + c0]       = v0;
            *(float2*)&O[(size_t)(r0 + 8) * Ec + c0] = v1;
        }
}

// ---------------- rotary + split q,k into per-head bf16 hi/lo ----------------
__global__ void k_theta_split() {
    int i = blockIdx.x * blockDim.x + threadIdx.x;
    if (i >= BSc * Ec / 2) return;
    int e2 = i % (Ec / 2);
    int bs = i / (Ec / 2);
    int e = e2 * 2;
    int h = e >> 6;
    int d = e & 63;
    int s = bs % Sc;
    int b = bs / Sc;
    float sn0 = g_sin[s * Dc + d], sn1 = g_sin[s * Dc + d + 1];
    float cs0 = g_cos[s * Dc + d], cs1 = g_cos[s * Dc + d + 1];
    size_t src = (size_t)bs * Ec + e;
    float q0 = g_q[src], q1 = g_q[src + 1];
    float qr0 = q0 * cs0 - q1 * sn0;
    float qr1 = q1 * cs1 + q0 * sn1;
    float k0 = g_k[src], k1 = g_k[src + 1];
    float kr0 = k0 * cs0 - k1 * sn0;
    float kr1 = k1 * cs1 + k0 * sn1;
    size_t dst = ((size_t)(b * Hc + h) * Sc + s) * Dc + d;
    __nv_bfloat16 a0 = __float2bfloat16(qr0), a1 = __float2bfloat16(qr1);
    *(__nv_bfloat162*)&g_qh[dst] = __nv_bfloat162(a0, a1);
    *(__nv_bfloat162*)&g_ql[dst] = __nv_bfloat162(
        __float2bfloat16(qr0 - __bfloat162float(a0)),
        __float2bfloat16(qr1 - __bfloat162float(a1)));
    __nv_bfloat16 c0 = __float2bfloat16(kr0), c1 = __float2bfloat16(kr1);
    *(__nv_bfloat162*)&g_kh[dst] = __nv_bfloat162(c0, c1);
    *(__nv_bfloat162*)&g_kl[dst] = __nv_bfloat162(
        __float2bfloat16(kr0 - __bfloat162float(c0)),
        __float2bfloat16(kr1 - __bfloat162float(c1)));
}

// ---------------- transpose + split V into [bh][d][s] fp16 hi/lo ----------------
__global__ void k_v_split_t() {
    __shared__ float t[32][33];
    int bh = blockIdx.z;
    int b = bh >> 4, h = bh & 15;
    int s0 = blockIdx.x * 32, d0 = blockIdx.y * 32;
    int tx = threadIdx.x, ty = threadIdx.y;   // 32 x 8
#pragma unroll
    for (int i = 0; i < 4; ++i)
        t[ty + i * 8][tx] = g_v[(size_t)(b * Sc + s0 + ty + i * 8) * Ec + h * 64 + d0 + tx];
    __syncthreads();
#pragma unroll
    for (int i = 0; i < 4; ++i) {
        float x = t[tx][ty + i * 8];   // (s = s0+tx, d = d0+ty+i*8)
        __half hi = __float2half(x);
        size_t dst = (size_t)bh * Dc * Sc + (size_t)(d0 + ty + i * 8) * Sc + s0 + tx;
        g_vth[dst] = hi;
        g_vtl[dst] = __float2half(x - __half2float(hi));
    }
}

// ---------------- fused retention via mma.sync ----------------
// GEMM1: bf16 3-term (qh/ql x kh/kl); GEMM2: fp16 2-term (fp16(S) x (vh+vl))
#define QK_STR 144     // 72 bf16 per row
#define VT_STR 272     // 136 fp16 per row
#define OQH 0
#define OQL 18432
#define OKH 36864
#define OKL 55296
#define OVH 73728
#define OVL 91136
#define ORS 108544     // rowsum: 2 x 128 floats
#define RSM_BYTES (ORS + 1024)

__global__ __launch_bounds__(256) void k_ret_mma() {
    extern __shared__ char smc[];
    uint32_t smb = smem_u32(smc);
    const int tid = threadIdx.x, wid = tid >> 5, lane = tid & 31;
    const int warpM = wid & 3, warpN = wid >> 2;
    const int bh = blockIdx.z;
    const int b = bh >> 4, h = bh & 15;
    const int qTile = 15 - (int)blockIdx.y;     // heavy first
    const int qRow0 = qTile * 128;
    const int lt = lane >> 3, lr = lane & 7;
    const int ldRow = (lt & 1) * 8 + lr;
    const int ldKB = (lt >> 1) * 16;
    const int r0 = lane >> 2;
    const int c2 = (lane & 3) * 2;

    const __nv_bfloat16* Qh = g_qh + (size_t)bh * Sc * Dc;
    const __nv_bfloat16* Ql = g_ql + (size_t)bh * Sc * Dc;
    const __nv_bfloat16* Kh = g_kh + (size_t)bh * Sc * Dc;
    const __nv_bfloat16* Kl = g_kl + (size_t)bh * Sc * Dc;
    const __half* Vh = g_vth + (size_t)bh * Dc * Sc;
    const __half* Vl = g_vtl + (size_t)bh * Dc * Sc;

    // load Q tiles once
#pragma unroll
    for (int i = 0; i < 4; ++i) {
        int s = tid + i * 256;
        int r = s >> 3, i8 = s & 7;
        *(uint4*)(smc + OQH + r * QK_STR + i8 * 16) =
            *(const uint4*)(Qh + (size_t)(qRow0 + r) * Dc + i8 * 8);
        *(uint4*)(smc + OQL + r * QK_STR + i8 * 16) =
            *(const uint4*)(Ql + (size_t)(qRow0 + r) * Dc + i8 * 8);
    }

    const float decay = logf(1.0f - exp2f(-(float)(5 + h)));
    float rowf[4];
#pragma unroll
    for (int i = 0; i < 4; ++i) {
        int row = warpM * 32 + (i >> 1) * 16 + (i & 1) * 8 + r0;
        int q = qRow0 + row;
        rowf[i] = expf((float)q * decay) * g_invnorm[h * Sc + q];
    }
    float colf[16];
#pragma unroll
    for (int nj = 0; nj < 8; ++nj)
#pragma unroll
        for (int e = 0; e < 2; ++e) {
            int cloc = warpN * 64 + nj * 8 + c2 + e;
            colf[nj * 2 + e] = expf(-(float)cloc * decay);
        }

    float acc2[2][8][4];
#pragma unroll
    for (int mi = 0; mi < 2; ++mi)
#pragma unroll
        for (int nj = 0; nj < 8; ++nj)
#pragma unroll
            for (int e = 0; e < 4; ++e) acc2[mi][nj][e] = 0.0f;
    float rsum[4] = {0.f, 0.f, 0.f, 0.f};

    __syncthreads();

    for (int kt = 0; kt <= qTile; ++kt) {
        const int kcol0 = kt * 128;
#pragma unroll
        for (int i = 0; i < 4; ++i) {
            int s = tid + i * 256;
            int r = s >> 3, i8 = s & 7;
            *(uint4*)(smc + OKH + r * QK_STR + i8 * 16) =
                *(const uint4*)(Kh + (size_t)(kcol0 + r) * Dc + i8 * 8);
            *(uint4*)(smc + OKL + r * QK_STR + i8 * 16) =
                *(const uint4*)(Kl + (size_t)(kcol0 + r) * Dc + i8 * 8);
        }
#pragma unroll
        for (int i = 0; i < 4; ++i) {
            int s = tid + i * 256;
            int r = s >> 4, i16 = s & 15;
            *(uint4*)(smc + OVH + r * VT_STR + i16 * 16) =
                *(const uint4*)(Vh + (size_t)r * Sc + kcol0 + i16 * 8);
            *(uint4*)(smc + OVL + r * VT_STR + i16 * 16) =
                *(const uint4*)(Vl + (size_t)r * Sc + kcol0 + i16 * 8);
        }
        __syncthreads();

        // ---- GEMM1: S = Q K^T (3 split terms, bf16) ----
        float acc[2][8][4];
#pragma unroll
        for (int mi = 0; mi < 2; ++mi)
#pragma unroll
            for (int nj = 0; nj < 8; ++nj)
#pragma unroll
                for (int e = 0; e < 4; ++e) acc[mi][nj][e] = 0.0f;
#pragma unroll
        for (int t = 0; t < 3; ++t) {
            uint32_t abase = smb + ((t < 2) ? OQH : OQL);
            uint32_t bbase = smb + ((t == 1) ? OKL : OKH);
#pragma unroll
            for (int s = 0; s < 4; ++s) {
                uint32_t a[2][4];
#pragma unroll
                for (int mi = 0; mi < 2; ++mi)
                    ldsm_x4(a[mi][0], a[mi][1], a[mi][2], a[mi][3],
                            abase + (warpM * 32 + mi * 16 + ldRow) * QK_STR + s * 32 + ldKB);
                uint32_t bt[4][4];
#pragma unroll
                for (int ng = 0; ng < 4; ++ng)
                    ldsm_x4(bt[ng][0], bt[ng][1], bt[ng][2], bt[ng][3],
                            bbase + (warpN * 64 + ng * 16 + ldRow) * QK_STR + s * 32 + ldKB);
#pragma unroll
                for (int mi = 0; mi < 2; ++mi)
#pragma unroll
                    for (int ng = 0; ng < 4; ++ng) {
                        mma_bf16(acc[mi][ng * 2 + 0], a[mi][0], a[mi][1], a[mi][2], a[mi][3],
                                 bt[ng][0], bt[ng][2]);
                        mma_bf16(acc[mi][ng * 2 + 1], a[mi][0], a[mi][1], a[mi][2], a[mi][3],
                                 bt[ng][1], bt[ng][3]);
                    }
            }
        }

        // ---- mask + rowsum + fp16 convert + GEMM2 per k16 slice ----
        const float ektf = expf(-(float)kcol0 * decay);
        const bool diag = (kt == qTile);
        float rk[4];
#pragma unroll
        for (int i = 0; i < 4; ++i) rk[i] = rowf[i] * ektf;

#pragma unroll
        for (int s = 0; s < 4; ++s) {
            uint32_t sA[2][4];
#pragma unroll
            for (int mi = 0; mi < 2; ++mi) {
                float sv[2][4];
#pragma unroll
                for (int p = 0; p < 2; ++p) {
                    int nj = 2 * s + p;
#pragma unroll
                    for (int e = 0; e < 4; ++e) {
                        int half = e >> 1;
                        float v = acc[mi][nj][e] * (rk[mi * 2 + half] * colf[nj * 2 + (e & 1)]);
                        if (diag) {
                            int rowl = warpM * 32 + mi * 16 + half * 8 + r0;
                            int cloc = warpN * 64 + nj * 8 + c2 + (e & 1);
                            if (cloc > rowl) v = 0.0f;
                        }
                        sv[p][e] = v;
                        rsum[mi * 2 + half] += fabsf(v);
                    }
                }
                sA[mi][0] = packh(sv[0][0], sv[0][1]);
                sA[mi][1] = packh(sv[0][2], sv[0][3]);
                sA[mi][2] = packh(sv[1][0], sv[1][1]);
                sA[mi][3] = packh(sv[1][2], sv[1][3]);
            }
            // V fragments: this warp's S columns are keys [kcol0 + warpN*64 + 16s, +16)
            uint32_t vh[4][4], vl[4][4];
#pragma unroll
            for (int ng = 0; ng < 4; ++ng) {
                ldsm_x4(vh[ng][0], vh[ng][1], vh[ng][2], vh[ng][3],
                        smb + OVH + (ng * 16 + ldRow) * VT_STR + warpN * 128 + s * 32 + ldKB);
                ldsm_x4(vl[ng][0], vl[ng][1], vl[ng][2], vl[ng][3],
                        smb + OVL + (ng * 16 + ldRow) * VT_STR + warpN * 128 + s * 32 + ldKB);
            }
#pragma unroll
            for (int mi = 0; mi < 2; ++mi)
#pragma unroll
                for (int ng = 0; ng < 4; ++ng) {
                    mma_fp16(acc2[mi][ng * 2 + 0], sA[mi][0], sA[mi][1], sA[mi][2], sA[mi][3],
                             vh[ng][0], vh[ng][2]);
                    mma_fp16(acc2[mi][ng * 2 + 1], sA[mi][0], sA[mi][1], sA[mi][2], sA[mi][3],
                             vh[ng][1], vh[ng][3]);
                    mma_fp16(acc2[mi][ng * 2 + 0], sA[mi][0], sA[mi][1], sA[mi][2], sA[mi][3],
                             vl[ng][0], vl[ng][2]);
                    mma_fp16(acc2[mi][ng * 2 + 1], sA[mi][0], sA[mi][1], sA[mi][2], sA[mi][3],
                             vl[ng][1], vl[ng][3]);
                }
        }
        __syncthreads();
    }

    // ---- epilogue ----
    float* RS = (float*)(smc + ORS);
#pragma unroll
    for (int i = 0; i < 4; ++i) {
        float v = rsum[i];
        v += __shfl_xor_sync(0xffffffffu, v, 1);
        v += __shfl_xor_sync(0xffffffffu, v, 2);
        rsum[i] = v;
    }
    if ((lane & 3) == 0) {
#pragma unroll
        for (int i = 0; i < 4; ++i)
            RS[warpN * 128 + warpM * 32 + (i >> 1) * 16 + (i & 1) * 8 + r0] = rsum[i];
    }
    __syncthreads();

    float* accS = (float*)smc;   // reuse Q region (dead after kt loop)
    if (warpN == 1) {
#pragma unroll
        for (int mi = 0; mi < 2; ++mi)
#pragma unroll
            for (int nj = 0; nj < 8; ++nj) {
                int rowl = warpM * 32 + mi * 16 + r0;
                *(float2*)&accS[(size_t)rowl * 64 + nj * 8 + c2] =
                    make_float2(acc2[mi][nj][0], acc2[mi][nj][1]);
                *(float2*)&accS[(size_t)(rowl + 8) * 64 + nj * 8 + c2] =
                    make_float2(acc2[mi][nj][2], acc2[mi][nj][3]);
            }
    }
    __syncthreads();
    if (warpN == 0) {
#pragma unroll
        for (int mi = 0; mi < 2; ++mi) {
            int rowl = warpM * 32 + mi * 16 + r0;
            float d0 = RS[rowl] + RS[128 + rowl];
            float d1 = RS[rowl + 8] + RS[128 + rowl + 8];
            float inv0 = 1.0f / fminf(fmaxf(d0, 1.0f), 50000.0f);
            float inv1 = 1.0f / fminf(fmaxf(d1, 1.0f), 50000.0f);
#pragma unroll
            for (int nj = 0; nj < 8; ++nj) {
                float2 p0 = *(float2*)&accS[(size_t)rowl * 64 + nj * 8 + c2];
                float2 p1 = *(float2*)&accS[(size_t)(rowl + 8) * 64 + nj * 8 + c2];
                float2 o0 = make_float2((acc2[mi][nj][0] + p0.x) * inv0,
                                        (acc2[mi][nj][1] + p0.y) * inv0);
                float2 o1 = make_float2((acc2[mi][nj][2] + p1.x) * inv1,
                                        (acc2[mi][nj][3] + p1.y) * inv1);
                int col = nj * 8 + c2;
                *(float2*)&g_av[(size_t)(b * Sc + qRow0 + rowl) * Ec + h * 64 + col] = o0;
                *(float2*)&g_av[(size_t)(b * Sc + qRow0 + rowl + 8) * Ec + h * 64 + col] = o1;
            }
        }
    }
}

// ---------------- RMSNorm over D, silu(g) gate, write output ----------------
__global__ void k_final(float* __restrict__ out) {
    __shared__ float warpsum[2];
    int bsh = blockIdx.x;
    int h = bsh & (Hc - 1);
    int bs = bsh >> 4;
    int d = threadIdx.x;
    size_t idx = (size_t)bs * Ec + h * Dc + d;
    float v = g_av[idx];
    float sq = v * v;
#pragma unroll
    for (int off = 16; off; off >>= 1) sq += __shfl_down_sync(0xffffffffu, sq, off);
    if ((d & 31) == 0) warpsum[d >> 5] = sq;
    __syncthreads();
    float total = warpsum[0] + warpsum[1];
    float scl = rsqrtf(total * (1.0f / 64.0f) + 1e-6f);
    float gg = g_g[idx];
    float silu = gg / (1.0f + expf(-gg));
    out[idx] = silu * v * scl;
}

// ---------------- launch ----------------
extern "C" void kernel_launch(void* const* d_in, const int* in_sizes, int n_in,
                              void* d_out, int out_size) {
    const float* x  = (const float*)d_in[0];
    const float* Wq = (const float*)d_in[1];
    const float* Wk = (const float*)d_in[2];
    const float* Wv = (const float*)d_in[3];
    const float* Wg = (const float*)d_in[4];
    float* out = (float*)d_out;

    cudaFuncSetAttribute(k_ret_mma, cudaFuncAttributeMaxDynamicSharedMemorySize, RSM_BYTES);

    k_sincos<<<(Sc * Dc + 255) / 256, 256>>>();
    k_norm<<<Hc, 256>>>();

    k_split_x<<<BSc * Ec / 256, 256>>>(x);
    k_split_w<<<dim3(Ec / 32, Ec / 32, 4), dim3(32, 8)>>>(Wq, Wk, Wv, Wg);

    k_gemm_mma<<<dim3(Ec / 128, BSc / 128, 4), 256>>>();

    k_theta_split<<<(BSc * Ec / 2 + 255) / 256, 256>>>();
    k_v_split_t<<<dim3(Sc / 32, Dc / 32, Bc * Hc), dim3(32, 8)>>>();

    k_ret_mma<<<dim3(1, 16, Bc * Hc), 256, RSM_BYTES>>>();

    k_final<<<Bc * Sc * Hc, Dc>>>(out);
}